// round 6
// baseline (speedup 1.0000x reference)
#include <cuda_runtime.h>

// DynamicConv2d: B=64, C=8, H=W=256, OUT_C=8, K=3, pad=1.
// R5: dual-shifted smem input tile => ALL three 3x1 taps are direct aligned
//     LDS.64 col-pairs; inner loop is pure LDS.64 + fma.rn.f32x2 (no movs).
//     copy A: col g at index g+4 (even)  -> middle tap (cx,cx+1)
//     copy B: col g at index g+3 (odd)   -> taps (cx-1,cx) and (cx+1,cx+2)
//     Duplicated (w,w) weight pairs load as broadcast LDS.64.

typedef unsigned long long u64;

#define TY 8                    // output rows per tile
#define TX 128                  // output cols per tile
#define SIN_STRIDE 136          // row stride in floats
#define SIN_ROWS (TY + 2)       // 10
#define SIN_PER_C (SIN_ROWS * SIN_STRIDE)      // 1360
#define SIN_COPY (8 * SIN_PER_C)               // 10880 floats per copy
#define SMEM_W 1152             // duplicated weights: 72*8*2
#define SMEM_FLOATS (SMEM_W + 2 * SIN_COPY)    // 22912
#define SMEM_BYTES (SMEM_FLOATS * 4)           // 91648

// Duplicated packed weights: [b][c*9+kk][o][2]; each weight stored twice so a
// single LDS.64 yields the (w,w) pair an f32x2 FMA needs.
__device__ __align__(16) float g_wdup[64 * 72 * 8 * 2];

__global__ void gen_weights_kernel(const float* __restrict__ dw,
                                   const float* __restrict__ Wg,
                                   const float* __restrict__ bg) {
    int b = blockIdx.x;
    int t = threadIdx.x;          // 0..575
    int j = t >> 3;               // c*9 + kk  (input-channel*9 + tap)
    int o = t & 7;                // output channel (torch .view quirk)
    const float* dwp = dw + (b * 8 + o) * 8;
    const float* wgp = Wg + j * 8;
    float v = bg[j];
#pragma unroll
    for (int i = 0; i < 8; i++) v = fmaf(dwp[i], wgp[i], v);
    float* dst = g_wdup + ((b * 72 + j) * 8 + o) * 2;
    dst[0] = v;
    dst[1] = v;
}

__global__ __launch_bounds__(256, 2)
void conv_kernel(const float* __restrict__ x, float* __restrict__ out) {
    extern __shared__ float sm[];
    float* sw = sm;                       // 1152 floats duplicated weights
    float* sA = sm + SMEM_W;              // copy A: col g at g+4 (even)
    float* sB = sA + SIN_COPY;            // copy B: col g at g+3 (odd)

    int bi = blockIdx.x;
    int b  = bi >> 6;              // batch
    int y0 = ((bi >> 1) & 31) * TY;
    int x0 = (bi & 1) * TX;
    int tx2 = threadIdx.x;         // col-pair index 0..63 -> cols 2*tx2, +1
    int g   = threadIdx.y;         // och-pair index 0..3 -> och 2g, 2g+1
    int tid = tx2 + (g << 6);      // 0..255

    // --- weights: 1152 floats = 288 float4 ---
    {
        const float4* wsrc = (const float4*)(g_wdup + b * 1152);
        if (tid < 144) {
            ((float4*)sw)[tid]       = wsrc[tid];
            ((float4*)sw)[tid + 144] = wsrc[tid + 144];
        }
    }

    // --- input tile: LDG.128, store to both shifted copies ---
    const float* xb = x + (size_t)b * (8 * 65536);
    {
        int w5 = tid >> 5;         // 0..7
        int q  = tid & 31;         // quad 0..31
#pragma unroll
        for (int pass = 0; pass < 10; pass++) {
            int row = pass * 8 + w5;      // 0..79 = c*10 + t
            int c = row / 10;
            int t = row - c * 10;
            int gy = y0 - 1 + t;
            float4 v = make_float4(0.f, 0.f, 0.f, 0.f);
            if ((unsigned)gy < 256u)
                v = *(const float4*)(xb + c * 65536 + gy * 256 + x0 + 4 * q);
            // copy A: aligned STS.128 at index 4q+4
            *(float4*)(sA + row * SIN_STRIDE + 4 * q + 4) = v;
            // copy B: scalar stores at index 4q+3
            float* dB = sB + row * SIN_STRIDE + 4 * q + 3;
            dB[0] = v.x; dB[1] = v.y; dB[2] = v.z; dB[3] = v.w;
        }
        // halo: left col -1 -> A@3, B@2 ; right col 128 -> A@132, B@131
        if (tid < 160) {
            int side = tid >= 80;
            int r = side ? tid - 80 : tid;     // 0..79
            int c = r / 10;
            int t = r - c * 10;
            int gy = y0 - 1 + t;
            int gx = side ? (x0 + 128) : (x0 - 1);
            float v = 0.f;
            if (((unsigned)gy < 256u) && ((unsigned)gx < 256u))
                v = __ldg(xb + c * 65536 + gy * 256 + gx);
            sA[r * SIN_STRIDE + (side ? 132 : 3)] = v;
            sB[r * SIN_STRIDE + (side ? 131 : 2)] = v;
        }
    }
    __syncthreads();

    // --- accumulate: acc[r][oo] packs cols (2tx2, 2tx2+1) for och 2g+oo ---
    u64 acc[TY][2];
#pragma unroll
    for (int r = 0; r < TY; r++) { acc[r][0] = 0ull; acc[r][1] = 0ull; }

    const u64* swq = (const u64*)sw;

#pragma unroll 1
    for (int c = 0; c < 8; c++) {
        // 18 duplicated weight pairs: [kh][kw][oo]  (broadcast LDS.64)
        u64 w[3][3][2];
#pragma unroll
        for (int kk = 0; kk < 9; kk++) {
#pragma unroll
            for (int oo = 0; oo < 2; oo++)
                w[kk / 3][kk % 3][oo] = swq[(c * 9 + kk) * 8 + 2 * g + oo];
        }
        const float* scA = sA + c * SIN_PER_C + 2 * tx2;
        const float* scB = sB + c * SIN_PER_C + 2 * tx2;
#pragma unroll
        for (int t = 0; t < SIN_ROWS; t++) {
            u64 q0 = *(const u64*)(scB + t * SIN_STRIDE + 2);  // (cx-1, cx)
            u64 pm = *(const u64*)(scA + t * SIN_STRIDE + 4);  // (cx,   cx+1)
            u64 q1 = *(const u64*)(scB + t * SIN_STRIDE + 4);  // (cx+1, cx+2)
#pragma unroll
            for (int kh = 0; kh < 3; kh++) {
                int r = t - kh;                  // output row this tap feeds
                if (r >= 0 && r < TY) {
#pragma unroll
                    for (int oo = 0; oo < 2; oo++) {
                        asm("fma.rn.f32x2 %0, %1, %2, %0;"
                            : "+l"(acc[r][oo]) : "l"(q0), "l"(w[kh][0][oo]));
                        asm("fma.rn.f32x2 %0, %1, %2, %0;"
                            : "+l"(acc[r][oo]) : "l"(pm), "l"(w[kh][1][oo]));
                        asm("fma.rn.f32x2 %0, %1, %2, %0;"
                            : "+l"(acc[r][oo]) : "l"(q1), "l"(w[kh][2][oo]));
                    }
                }
            }
        }
    }

    // --- write out: STG.64 per (row, och) ---
    float* ob = out + (size_t)b * (8 * 65536) + x0 + 2 * tx2;
#pragma unroll
    for (int r = 0; r < TY; r++) {
#pragma unroll
        for (int oo = 0; oo < 2; oo++) {
            int och = 2 * g + oo;
            *(u64*)(ob + och * 65536 + (y0 + r) * 256) = acc[r][oo];
        }
    }
}

extern "C" void kernel_launch(void* const* d_in, const int* in_sizes, int n_in,
                              void* d_out, int out_size) {
    const float* x  = (const float*)d_in[0];
    const float* dw = (const float*)d_in[1];
    const float* Wg = (const float*)d_in[2];
    const float* bg = (const float*)d_in[3];
    float* out = (float*)d_out;

    cudaFuncSetAttribute(conv_kernel, cudaFuncAttributeMaxDynamicSharedMemorySize,
                         SMEM_BYTES);

    gen_weights_kernel<<<64, 576>>>(dw, Wg, bg);

    dim3 blk(64, 4, 1);
    conv_kernel<<<64 * 32 * 2, blk, SMEM_BYTES>>>(x, out);
}

// round 7
// speedup vs baseline: 1.0336x; 1.0336x over previous
#include <cuda_runtime.h>

// DynamicConv2d: B=64, C=8, H=W=256, OUT_C=8, K=3, pad=1.
// R6: col-pair f32x2 (R4 structure) with minimal aux:
//     q0/q1 as plain LDS.64 (halves are register-pair renames),
//     pm built with ONE mov.b64 (2 MOV32) from q0.hi/q1.lo.
//     Per (c,t): 2 LDS.64 + 2 MOV + 18 FFMA2. 3 CTAs/SM.

typedef unsigned long long u64;

#define TY 8                    // output rows per tile
#define TX 128                  // output cols per tile
#define SIN_STRIDE 136          // row stride (floats); col cx stored at cx+3
#define SIN_ROWS (TY + 2)       // 10
#define SIN_PER_C (SIN_ROWS * SIN_STRIDE)     // 1360
#define SMEM_W 1152             // duplicated weights: 72*8*2
#define SMEM_FLOATS (SMEM_W + 8 * SIN_PER_C)  // 12032
#define SMEM_BYTES (SMEM_FLOATS * 4)          // 48128

// Duplicated packed weights: [b][c*9+kk][o][2]; each weight stored twice so a
// single broadcast LDS.64 yields the (w,w) splat an f32x2 FMA needs.
__device__ __align__(16) float g_wdup[64 * 72 * 8 * 2];

__global__ void gen_weights_kernel(const float* __restrict__ dw,
                                   const float* __restrict__ Wg,
                                   const float* __restrict__ bg) {
    int b = blockIdx.x;
    int t = threadIdx.x;          // 0..575
    int j = t >> 3;               // c*9 + kk  (input-channel*9 + tap)
    int o = t & 7;                // output channel (torch .view quirk)
    const float* dwp = dw + (b * 8 + o) * 8;
    const float* wgp = Wg + j * 8;
    float v = bg[j];
#pragma unroll
    for (int i = 0; i < 8; i++) v = fmaf(dwp[i], wgp[i], v);
    float* dst = g_wdup + ((b * 72 + j) * 8 + o) * 2;
    dst[0] = v;
    dst[1] = v;
}

__global__ __launch_bounds__(256, 3)
void conv_kernel(const float* __restrict__ x, float* __restrict__ out) {
    extern __shared__ float sm[];
    float* sw  = sm;               // 1152 floats duplicated weights
    float* sin = sm + SMEM_W;      // 8 ch x 10 rows x 136 (odd layout: col g at g+3)

    int bi = blockIdx.x;
    int b  = bi >> 6;              // batch
    int y0 = ((bi >> 1) & 31) * TY;
    int x0 = (bi & 1) * TX;
    int tx2 = threadIdx.x;         // col-pair index 0..63 -> cols 2*tx2, +1
    int g   = threadIdx.y;         // och-pair index 0..3 -> och 2g, 2g+1
    int tid = tx2 + (g << 6);      // 0..255

    // --- weights: 1152 floats = 288 float4 ---
    {
        const float4* wsrc = (const float4*)(g_wdup + b * 1152);
        if (tid < 144) {
            ((float4*)sw)[tid]       = wsrc[tid];
            ((float4*)sw)[tid + 144] = wsrc[tid + 144];
        }
    }

    // --- input tile: interior via LDG.128, scalar STS (odd base offset 3) ---
    const float* xb = x + (size_t)b * (8 * 65536);
    {
        int w5 = tid >> 5;         // 0..7
        int q  = tid & 31;         // quad 0..31
#pragma unroll
        for (int pass = 0; pass < 10; pass++) {
            int row = pass * 8 + w5;      // 0..79 = c*10 + t
            int c = row / 10;
            int t = row - c * 10;
            int gy = y0 - 1 + t;
            float4 v = make_float4(0.f, 0.f, 0.f, 0.f);
            if ((unsigned)gy < 256u)
                v = *(const float4*)(xb + c * 65536 + gy * 256 + x0 + 4 * q);
            float* d = sin + row * SIN_STRIDE + 4 * q + 3;
            d[0] = v.x; d[1] = v.y; d[2] = v.z; d[3] = v.w;
        }
        // halo: left (x0-1) -> pos 2, right (x0+128) -> pos 131
        if (tid < 160) {
            int side = tid >= 80;
            int r = side ? tid - 80 : tid;     // 0..79
            int c = r / 10;
            int t = r - c * 10;
            int gy = y0 - 1 + t;
            int gx = side ? (x0 + 128) : (x0 - 1);
            float v = 0.f;
            if (((unsigned)gy < 256u) && ((unsigned)gx < 256u))
                v = __ldg(xb + c * 65536 + gy * 256 + gx);
            sin[r * SIN_STRIDE + (side ? 131 : 2)] = v;
        }
    }
    __syncthreads();

    // --- accumulate: acc[r][oo] packs cols (2tx2, 2tx2+1) for och 2g+oo ---
    u64 acc[TY][2];
#pragma unroll
    for (int r = 0; r < TY; r++) { acc[r][0] = 0ull; acc[r][1] = 0ull; }

    const u64* swq = (const u64*)sw;

#pragma unroll 1
    for (int c = 0; c < 8; c++) {
        // 18 duplicated weight splats: [kh][kw][oo]  (broadcast LDS.64)
        u64 w[3][3][2];
#pragma unroll
        for (int kk = 0; kk < 9; kk++) {
#pragma unroll
            for (int oo = 0; oo < 2; oo++)
                w[kk / 3][kk % 3][oo] = swq[(c * 9 + kk) * 8 + 2 * g + oo];
        }
        const float* sc = sin + c * SIN_PER_C + 2 * tx2;
#pragma unroll
        for (int t = 0; t < SIN_ROWS; t++) {
            const float* rowp = sc + t * SIN_STRIDE;
            u64 q0 = *(const u64*)(rowp + 2);   // (cx-1, cx)   aligned LDS.64
            u64 q1 = *(const u64*)(rowp + 4);   // (cx+1, cx+2) aligned LDS.64
            u64 pm;                              // (cx, cx+1) = {q0.hi, q1.lo}
            asm("mov.b64 %0, {%1, %2};" : "=l"(pm)
                : "r"((unsigned)(q0 >> 32)), "r"((unsigned)q1));
#pragma unroll
            for (int kh = 0; kh < 3; kh++) {
                int r = t - kh;                  // output row this tap feeds
                if (r >= 0 && r < TY) {
#pragma unroll
                    for (int oo = 0; oo < 2; oo++) {
                        asm("fma.rn.f32x2 %0, %1, %2, %0;"
                            : "+l"(acc[r][oo]) : "l"(q0), "l"(w[kh][0][oo]));
                        asm("fma.rn.f32x2 %0, %1, %2, %0;"
                            : "+l"(acc[r][oo]) : "l"(pm), "l"(w[kh][1][oo]));
                        asm("fma.rn.f32x2 %0, %1, %2, %0;"
                            : "+l"(acc[r][oo]) : "l"(q1), "l"(w[kh][2][oo]));
                    }
                }
            }
        }
    }

    // --- write out: STG.64 per (row, och) ---
    float* ob = out + (size_t)b * (8 * 65536) + x0 + 2 * tx2;
#pragma unroll
    for (int r = 0; r < TY; r++) {
#pragma unroll
        for (int oo = 0; oo < 2; oo++) {
            int och = 2 * g + oo;
            *(u64*)(ob + och * 65536 + (y0 + r) * 256) = acc[r][oo];
        }
    }
}

extern "C" void kernel_launch(void* const* d_in, const int* in_sizes, int n_in,
                              void* d_out, int out_size) {
    const float* x  = (const float*)d_in[0];
    const float* dw = (const float*)d_in[1];
    const float* Wg = (const float*)d_in[2];
    const float* bg = (const float*)d_in[3];
    float* out = (float*)d_out;

    cudaFuncSetAttribute(conv_kernel, cudaFuncAttributeMaxDynamicSharedMemorySize,
                         SMEM_BYTES);

    gen_weights_kernel<<<64, 576>>>(dw, Wg, bg);

    dim3 blk(64, 4, 1);
    conv_kernel<<<64 * 32 * 2, blk, SMEM_BYTES>>>(x, out);
}

// round 8
// speedup vs baseline: 1.1832x; 1.1447x over previous
#include <cuda_runtime.h>

// DynamicConv2d: B=64, C=8, H=W=256, OUT_C=8, K=3, pad=1.
// R7: och-pair f32x2 (R2's low-alu inner loop: 3 LDS.32 + 3 splat-MOV +
//     18 FFMA2 per (c,t); natural weight pairs, no duplication) combined
//     with 3 CTAs/SM (__launch_bounds__(256,3)) and the fast pass-based
//     loader with aligned STS.128 interior stores.

typedef unsigned long long u64;

#define TY 8                    // output rows per tile
#define TX 128                  // output cols per tile
#define SIN_STRIDE 136          // row stride (floats); col g stored at g+4
#define SIN_ROWS (TY + 2)       // 10
#define SIN_PER_C (SIN_ROWS * SIN_STRIDE)     // 1360
#define SMEM_W 576              // natural packed weights: 72*8
#define SMEM_FLOATS (SMEM_W + 8 * SIN_PER_C)  // 11456
#define SMEM_BYTES (SMEM_FLOATS * 4)          // 45824

// Packed weight scratch: [b][c*9+kk][o], o fastest => och pairs are 8-byte
// aligned LDS.64 after copy to smem.
__device__ __align__(16) float g_wpack[64 * 72 * 8];

__global__ void gen_weights_kernel(const float* __restrict__ dw,
                                   const float* __restrict__ Wg,
                                   const float* __restrict__ bg) {
    int b = blockIdx.x;
    int t = threadIdx.x;          // 0..575
    int j = t >> 3;               // c*9 + kk
    int o = t & 7;                // output channel (torch .view quirk)
    const float* dwp = dw + (b * 8 + o) * 8;
    const float* wgp = Wg + j * 8;
    float v = bg[j];
#pragma unroll
    for (int i = 0; i < 8; i++) v = fmaf(dwp[i], wgp[i], v);
    g_wpack[(b * 72 + j) * 8 + o] = v;
}

__global__ __launch_bounds__(256, 3)
void conv_kernel(const float* __restrict__ x, float* __restrict__ out) {
    extern __shared__ float sm[];
    float* sw  = sm;               // 576 floats packed weights
    float* sin = sm + SMEM_W;      // 8 ch x 10 rows x 136; col g at g+4

    int bi = blockIdx.x;
    int b  = bi >> 6;              // batch
    int y0 = ((bi >> 1) & 31) * TY;
    int x0 = (bi & 1) * TX;
    int tx   = threadIdx.x;        // column within tile 0..127
    int half = threadIdx.y;        // och half: 0 -> och 0..3, 1 -> och 4..7
    int tid  = tx + (half << 7);   // 0..255

    // --- weights: 576 floats = 144 float4 ---
    if (tid < 144) {
        const float4* wsrc = (const float4*)(g_wpack + b * 576);
        ((float4*)sw)[tid] = wsrc[tid];
    }

    // --- input tile: LDG.128 + aligned STS.128 (col g at index g+4) ---
    const float* xb = x + (size_t)b * (8 * 65536);
    {
        int w5 = tid >> 5;         // 0..7
        int q  = tid & 31;         // quad 0..31
#pragma unroll
        for (int pass = 0; pass < 10; pass++) {
            int row = pass * 8 + w5;      // 0..79 = c*10 + t
            int c = row / 10;
            int t = row - c * 10;
            int gy = y0 - 1 + t;
            float4 v = make_float4(0.f, 0.f, 0.f, 0.f);
            if ((unsigned)gy < 256u)
                v = *(const float4*)(xb + c * 65536 + gy * 256 + x0 + 4 * q);
            *(float4*)(sin + row * SIN_STRIDE + 4 * q + 4) = v;
        }
        // halo: left (x0-1) -> idx 3, right (x0+128) -> idx 132
        if (tid < 160) {
            int side = tid >= 80;
            int r = side ? tid - 80 : tid;     // 0..79
            int c = r / 10;
            int t = r - c * 10;
            int gy = y0 - 1 + t;
            int gx = side ? (x0 + 128) : (x0 - 1);
            float v = 0.f;
            if (((unsigned)gy < 256u) && ((unsigned)gx < 256u))
                v = __ldg(xb + c * 65536 + gy * 256 + gx);
            sin[r * SIN_STRIDE + (side ? 132 : 3)] = v;
        }
    }
    __syncthreads();

    // --- accumulate: acc[r][p] packs och (2*(2*half+p), +1) for this col ---
    u64 acc[TY][2];
#pragma unroll
    for (int r = 0; r < TY; r++) { acc[r][0] = 0ull; acc[r][1] = 0ull; }

    const u64* swq = (const u64*)sw;

#pragma unroll 1
    for (int c = 0; c < 8; c++) {
        // 18 natural weight pairs: [tap][p]  (uniform LDS.64 across the warp)
        u64 w[9][2];
#pragma unroll
        for (int kk = 0; kk < 9; kk++) {
#pragma unroll
            for (int p = 0; p < 2; p++)
                w[kk][p] = swq[(c * 9 + kk) * 4 + half * 2 + p];
        }
        const float* sc = sin + c * SIN_PER_C + tx;
#pragma unroll
        for (int t = 0; t < SIN_ROWS; t++) {
            float v0 = sc[t * SIN_STRIDE + 3];   // col cx-1
            float v1 = sc[t * SIN_STRIDE + 4];   // col cx
            float v2 = sc[t * SIN_STRIDE + 5];   // col cx+1
            u64 d0, d1, d2;                      // (v,v) splats: 1 MOV each
            asm("mov.b64 %0, {%1, %1};" : "=l"(d0) : "f"(v0));
            asm("mov.b64 %0, {%1, %1};" : "=l"(d1) : "f"(v1));
            asm("mov.b64 %0, {%1, %1};" : "=l"(d2) : "f"(v2));
#pragma unroll
            for (int kh = 0; kh < 3; kh++) {
                int r = t - kh;                  // output row this tap feeds
                if (r >= 0 && r < TY) {
#pragma unroll
                    for (int p = 0; p < 2; p++) {
                        asm("fma.rn.f32x2 %0, %1, %2, %0;"
                            : "+l"(acc[r][p]) : "l"(d0), "l"(w[kh * 3 + 0][p]));
                        asm("fma.rn.f32x2 %0, %1, %2, %0;"
                            : "+l"(acc[r][p]) : "l"(d1), "l"(w[kh * 3 + 1][p]));
                        asm("fma.rn.f32x2 %0, %1, %2, %0;"
                            : "+l"(acc[r][p]) : "l"(d2), "l"(w[kh * 3 + 2][p]));
                    }
                }
            }
        }
    }

    // --- write out: acc[r][p] = (och 2q, och 2q+1), scalar STG each ---
    float* ob = out + (size_t)b * (8 * 65536) + x0;
#pragma unroll
    for (int r = 0; r < TY; r++) {
#pragma unroll
        for (int p = 0; p < 2; p++) {
            int q = half * 2 + p;
            unsigned lo, hi;
            asm("mov.b64 {%0, %1}, %2;" : "=r"(lo), "=r"(hi) : "l"(acc[r][p]));
            ob[(2 * q + 0) * 65536 + (y0 + r) * 256 + tx] = __uint_as_float(lo);
            ob[(2 * q + 1) * 65536 + (y0 + r) * 256 + tx] = __uint_as_float(hi);
        }
    }
}

extern "C" void kernel_launch(void* const* d_in, const int* in_sizes, int n_in,
                              void* d_out, int out_size) {
    const float* x  = (const float*)d_in[0];
    const float* dw = (const float*)d_in[1];
    const float* Wg = (const float*)d_in[2];
    const float* bg = (const float*)d_in[3];
    float* out = (float*)d_out;

    cudaFuncSetAttribute(conv_kernel, cudaFuncAttributeMaxDynamicSharedMemorySize,
                         SMEM_BYTES);

    gen_weights_kernel<<<64, 576>>>(dw, Wg, bg);

    dim3 blk(128, 2, 1);
    conv_kernel<<<64 * 32 * 2, blk, SMEM_BYTES>>>(x, out);
}